// round 12
// baseline (speedup 1.0000x reference)
#include <cuda_runtime.h>
#include <cuda_fp16.h>
#include <cstdint>

#define NUM_USERS 200000
#define NUM_ITEMS 100000
#define NUM_NODES (NUM_USERS + NUM_ITEMS)
#define EMBED_DIM 64
#define NUM_EDGES 2000000

#define SCAN_CHUNK 1024
#define NUM_SCAN_BLOCKS ((NUM_NODES + SCAN_CHUNK - 1) / SCAN_CHUNK)  // 293

// ---- device-global scratch (no allocation allowed) ----
__device__ int   g_deg[NUM_NODES];
__device__ int   g_off[NUM_NODES + 1];
__device__ int   g_pos[NUM_NODES];
__device__ int   g_bsum[512];
__device__ int2  g_edge[NUM_EDGES];                 // packed (src, weight-bits)
__device__ uint4 g_x0h[(size_t)NUM_NODES * 8];      // x0 in fp16: 8 halves per uint4
__device__ uint4 g_x1h[(size_t)NUM_NODES * 8];      // x1 in fp16

__device__ __forceinline__ const float* x0_row_ptr(int s, const float* u, const float* it) {
    return (s < NUM_USERS) ? (u + (size_t)s * EMBED_DIM)
                           : (it + (size_t)(s - NUM_USERS) * EMBED_DIM);
}

struct F8 { float v[8]; };

__device__ __forceinline__ F8 unpack_h8(uint4 pk) {
    F8 r;
    float2 f0 = __half22float2(*(const __half2*)&pk.x);
    float2 f1 = __half22float2(*(const __half2*)&pk.y);
    float2 f2 = __half22float2(*(const __half2*)&pk.z);
    float2 f3 = __half22float2(*(const __half2*)&pk.w);
    r.v[0] = f0.x; r.v[1] = f0.y; r.v[2] = f1.x; r.v[3] = f1.y;
    r.v[4] = f2.x; r.v[5] = f2.y; r.v[6] = f3.x; r.v[7] = f3.y;
    return r;
}

__device__ __forceinline__ uint4 pack_h8(const float* a) {
    __half2 h0 = __floats2half2_rn(a[0], a[1]);
    __half2 h1 = __floats2half2_rn(a[2], a[3]);
    __half2 h2 = __floats2half2_rn(a[4], a[5]);
    __half2 h3 = __floats2half2_rn(a[6], a[7]);
    uint4 pk;
    pk.x = *(const unsigned int*)&h0;
    pk.y = *(const unsigned int*)&h1;
    pk.z = *(const unsigned int*)&h2;
    pk.w = *(const unsigned int*)&h3;
    return pk;
}

#define CONV_THREADS ((long long)NUM_NODES * 8)
#define CONV_BLOCKS  ((int)((CONV_THREADS + 255) / 256))
#define HIST_BLOCKS  ((NUM_EDGES + 255) / 256)

// ---- 0+1 fused: convert x0 -> fp16 (blocks [0, CONV_BLOCKS)) and
//      histogram of dst degrees (blocks [CONV_BLOCKS, CONV_BLOCKS+HIST_BLOCKS)) ----
__global__ void convert_hist_kernel(const float* __restrict__ u_embs,
                                    const float* __restrict__ i_embs,
                                    const int* __restrict__ edge_dst) {
    if (blockIdx.x < CONV_BLOCKS) {
        long long gid = (long long)blockIdx.x * blockDim.x + threadIdx.x;
        if (gid >= CONV_THREADS) return;
        int n = (int)(gid >> 3);
        int c = (int)(gid & 7);
        const float* row = x0_row_ptr(n, u_embs, i_embs);
        float4 a = *(const float4*)(row + c * 8);
        float4 b = *(const float4*)(row + c * 8 + 4);
        float f[8] = {a.x, a.y, a.z, a.w, b.x, b.y, b.z, b.w};
        g_x0h[gid] = pack_h8(f);
    } else {
        int e = (blockIdx.x - CONV_BLOCKS) * blockDim.x + threadIdx.x;
        if (e >= NUM_EDGES) return;
        atomicAdd(&g_deg[__ldg(edge_dst + e)], 1);
    }
}

// ---- 2a. per-chunk sums ----
__global__ void block_sum_kernel() {
    __shared__ int s[SCAN_CHUNK];
    int t = threadIdx.x;
    int idx = blockIdx.x * SCAN_CHUNK + t;
    s[t] = (idx < NUM_NODES) ? g_deg[idx] : 0;
    __syncthreads();
    for (int o = SCAN_CHUNK / 2; o > 0; o >>= 1) {
        if (t < o) s[t] += s[t + o];
        __syncthreads();
    }
    if (t == 0) g_bsum[blockIdx.x] = s[0];
}

// ---- 2b. offsets: per-chunk scan + self-computed (lookback) chunk base ----
__global__ void offsets_kernel() {
    __shared__ int s[SCAN_CHUNK];
    __shared__ int base_sh;
    int t = threadIdx.x;

    // Phase A: base = sum of g_bsum[0 .. blockIdx.x-1] (parallel tree reduce)
    s[t] = (t < blockIdx.x) ? g_bsum[t] : 0;   // blockIdx.x <= 292 < 1024
    __syncthreads();
    for (int o = SCAN_CHUNK / 2; o > 0; o >>= 1) {
        if (t < o) s[t] += s[t + o];
        __syncthreads();
    }
    if (t == 0) base_sh = s[0];
    __syncthreads();

    // Phase B: chunk-local inclusive scan of degrees
    int idx = blockIdx.x * SCAN_CHUNK + t;
    int v = (idx < NUM_NODES) ? g_deg[idx] : 0;
    s[t] = v;
    __syncthreads();
    for (int o = 1; o < SCAN_CHUNK; o <<= 1) {
        int x = (t >= o) ? s[t - o] : 0;
        __syncthreads();
        s[t] += x;
        __syncthreads();
    }
    int excl = s[t] - v + base_sh;
    if (idx < NUM_NODES) {
        g_off[idx] = excl;
        g_pos[idx] = excl;
        if (idx == NUM_NODES - 1) g_off[NUM_NODES] = excl + v;
    }
}

// ---- 3. bucket edges by dst: one packed 8B store per edge ----
__global__ void bucket_kernel(const int* __restrict__ edge_src,
                              const int* __restrict__ edge_dst,
                              const float* __restrict__ edge_weight) {
    int e = blockIdx.x * blockDim.x + threadIdx.x;
    if (e >= NUM_EDGES) return;
    int d = __ldg(edge_dst + e);
    int p = atomicAdd(&g_pos[d], 1);
    int2 pk;
    pk.x = __ldg(edge_src + e);
    pk.y = __float_as_int(__ldg(edge_weight + e));
    g_edge[p] = pk;
}

// ---- 4. layer-1 gather: 4 lanes/node, each lane owns 32B (2x uint4) ----
__global__ void gather1_kernel() {
    long long gid = (long long)blockIdx.x * blockDim.x + threadIdx.x;
    int n = (int)(gid >> 2);
    int c = (int)(gid & 3);
    if (n >= NUM_NODES) return;

    int b = __ldg(&g_off[n]);
    int e = __ldg(&g_off[n + 1]);
    size_t cbase = (size_t)c * 2;

    float acc[16];
    #pragma unroll
    for (int i = 0; i < 16; i++) acc[i] = 0.f;

    int k = b;
    for (; k + 1 < e; k += 2) {
        int2 e0 = g_edge[k], e1 = g_edge[k + 1];
        const uint4* r0 = &g_x0h[(size_t)e0.x * 8 + cbase];
        const uint4* r1 = &g_x0h[(size_t)e1.x * 8 + cbase];
        uint4 p0a = r0[0], p0b = r0[1];
        uint4 p1a = r1[0], p1b = r1[1];
        float w0 = __int_as_float(e0.y), w1 = __int_as_float(e1.y);
        F8 v0a = unpack_h8(p0a), v0b = unpack_h8(p0b);
        F8 v1a = unpack_h8(p1a), v1b = unpack_h8(p1b);
        #pragma unroll
        for (int i = 0; i < 8; i++) {
            acc[i]     += w0 * v0a.v[i] + w1 * v1a.v[i];
            acc[i + 8] += w0 * v0b.v[i] + w1 * v1b.v[i];
        }
    }
    if (k < e) {
        int2 e0 = g_edge[k];
        float w0 = __int_as_float(e0.y);
        const uint4* r0 = &g_x0h[(size_t)e0.x * 8 + cbase];
        F8 v0a = unpack_h8(r0[0]), v0b = unpack_h8(r0[1]);
        #pragma unroll
        for (int i = 0; i < 8; i++) {
            acc[i]     += w0 * v0a.v[i];
            acc[i + 8] += w0 * v0b.v[i];
        }
    }
    g_x1h[(size_t)n * 8 + cbase]     = pack_h8(acc);
    g_x1h[(size_t)n * 8 + cbase + 1] = pack_h8(acc + 8);
}

// ---- 5. layer-2 gather (fp16 rows) fused with finalize (fp32 x0 + out) ----
__global__ void gather2_fin_kernel(const float* __restrict__ u_embs,
                                   const float* __restrict__ i_embs,
                                   float* __restrict__ out) {
    long long gid = (long long)blockIdx.x * blockDim.x + threadIdx.x;
    int n = (int)(gid >> 2);
    int c = (int)(gid & 3);
    if (n >= NUM_NODES) return;

    int b = __ldg(&g_off[n]);
    int e = __ldg(&g_off[n + 1]);
    size_t cbase = (size_t)c * 2;

    float acc[16];
    #pragma unroll
    for (int i = 0; i < 16; i++) acc[i] = 0.f;

    int k = b;
    for (; k + 1 < e; k += 2) {
        int2 e0 = g_edge[k], e1 = g_edge[k + 1];
        const uint4* r0 = &g_x1h[(size_t)e0.x * 8 + cbase];
        const uint4* r1 = &g_x1h[(size_t)e1.x * 8 + cbase];
        uint4 p0a = r0[0], p0b = r0[1];
        uint4 p1a = r1[0], p1b = r1[1];
        float w0 = __int_as_float(e0.y), w1 = __int_as_float(e1.y);
        F8 v0a = unpack_h8(p0a), v0b = unpack_h8(p0b);
        F8 v1a = unpack_h8(p1a), v1b = unpack_h8(p1b);
        #pragma unroll
        for (int i = 0; i < 8; i++) {
            acc[i]     += w0 * v0a.v[i] + w1 * v1a.v[i];
            acc[i + 8] += w0 * v0b.v[i] + w1 * v1b.v[i];
        }
    }
    if (k < e) {
        int2 e0 = g_edge[k];
        float w0 = __int_as_float(e0.y);
        const uint4* r0 = &g_x1h[(size_t)e0.x * 8 + cbase];
        F8 v0a = unpack_h8(r0[0]), v0b = unpack_h8(r0[1]);
        #pragma unroll
        for (int i = 0; i < 8; i++) {
            acc[i]     += w0 * v0a.v[i];
            acc[i + 8] += w0 * v0b.v[i];
        }
    }

    // finalize: fp32 x0 row + fp16 x1 row + acc, all /3
    const float* x0_row = x0_row_ptr(n, u_embs, i_embs) + c * 16;
    F8 b1a = unpack_h8(g_x1h[(size_t)n * 8 + cbase]);
    F8 b1b = unpack_h8(g_x1h[(size_t)n * 8 + cbase + 1]);

    const float inv3 = 1.0f / 3.0f;
    float* out_row = out + (size_t)n * EMBED_DIM + c * 16;
    #pragma unroll
    for (int q = 0; q < 2; q++) {
        float4 a0 = *(const float4*)(x0_row + q * 8);
        float4 a1 = *(const float4*)(x0_row + q * 8 + 4);
        const F8& bb = q ? b1b : b1a;
        const float* ac = acc + q * 8;
        float4 r0, r1;
        r0.x = (a0.x + bb.v[0] + ac[0]) * inv3;
        r0.y = (a0.y + bb.v[1] + ac[1]) * inv3;
        r0.z = (a0.z + bb.v[2] + ac[2]) * inv3;
        r0.w = (a0.w + bb.v[3] + ac[3]) * inv3;
        r1.x = (a1.x + bb.v[4] + ac[4]) * inv3;
        r1.y = (a1.y + bb.v[5] + ac[5]) * inv3;
        r1.z = (a1.z + bb.v[6] + ac[6]) * inv3;
        r1.w = (a1.w + bb.v[7] + ac[7]) * inv3;
        *(float4*)(out_row + q * 8)     = r0;
        *(float4*)(out_row + q * 8 + 4) = r1;
    }
}

extern "C" void kernel_launch(void* const* d_in, const int* in_sizes, int n_in,
                              void* d_out, int out_size) {
    const float* u_embs      = (const float*)d_in[0];
    const float* i_embs      = (const float*)d_in[1];
    const int*   edge_src    = (const int*)d_in[2];
    const int*   edge_dst    = (const int*)d_in[3];
    const float* edge_weight = (const float*)d_in[4];
    float* out = (float*)d_out;

    void* deg_ptr = nullptr;
    cudaGetSymbolAddress(&deg_ptr, g_deg);
    cudaMemsetAsync(deg_ptr, 0, NUM_NODES * sizeof(int), 0);

    // fused convert + histogram (independent work, one launch)
    convert_hist_kernel<<<CONV_BLOCKS + HIST_BLOCKS, 256>>>(u_embs, i_embs, edge_dst);

    // chunk sums, then offsets with self-computed base
    block_sum_kernel<<<NUM_SCAN_BLOCKS, SCAN_CHUNK>>>();
    offsets_kernel<<<NUM_SCAN_BLOCKS, SCAN_CHUNK>>>();

    // bucket edges by dst (packed 8B store)
    bucket_kernel<<<(NUM_EDGES + 255) / 256, 256>>>(edge_src, edge_dst, edge_weight);

    // layer 1 gather (fp16 in/out, 4 lanes per node)
    {
        long long total = (long long)NUM_NODES * 4;
        int threads = 256;
        int blocks = (int)((total + threads - 1) / threads);
        gather1_kernel<<<blocks, threads>>>();
    }

    // layer 2 gather + finalize
    {
        long long total = (long long)NUM_NODES * 4;
        int threads = 256;
        int blocks = (int)((total + threads - 1) / threads);
        gather2_fin_kernel<<<blocks, threads>>>(u_embs, i_embs, out);
    }
}

// round 13
// speedup vs baseline: 1.0356x; 1.0356x over previous
#include <cuda_runtime.h>
#include <cuda_fp16.h>
#include <cstdint>

#define NUM_USERS 200000
#define NUM_ITEMS 100000
#define NUM_NODES (NUM_USERS + NUM_ITEMS)
#define EMBED_DIM 64
#define NUM_EDGES 2000000

#define SCAN_CHUNK 1024
#define NUM_SCAN_BLOCKS ((NUM_NODES + SCAN_CHUNK - 1) / SCAN_CHUNK)  // 293

// ---- device-global scratch (no allocation allowed) ----
__device__ int   g_deg[NUM_NODES];
__device__ int   g_off[NUM_NODES + 1];
__device__ int   g_pos[NUM_NODES];
__device__ int   g_bsum[512];
__device__ int2  g_edge[NUM_EDGES];                 // packed (src, weight-bits)
__device__ uint4 g_x0h[(size_t)NUM_NODES * 8];      // x0 in fp16: 8 halves per uint4
__device__ uint4 g_x1h[(size_t)NUM_NODES * 8];      // x1 in fp16

__device__ __forceinline__ const float* x0_row_ptr(int s, const float* u, const float* it) {
    return (s < NUM_USERS) ? (u + (size_t)s * EMBED_DIM)
                           : (it + (size_t)(s - NUM_USERS) * EMBED_DIM);
}

struct F8 { float v[8]; };

__device__ __forceinline__ F8 unpack_h8(uint4 pk) {
    F8 r;
    float2 f0 = __half22float2(*(const __half2*)&pk.x);
    float2 f1 = __half22float2(*(const __half2*)&pk.y);
    float2 f2 = __half22float2(*(const __half2*)&pk.z);
    float2 f3 = __half22float2(*(const __half2*)&pk.w);
    r.v[0] = f0.x; r.v[1] = f0.y; r.v[2] = f1.x; r.v[3] = f1.y;
    r.v[4] = f2.x; r.v[5] = f2.y; r.v[6] = f3.x; r.v[7] = f3.y;
    return r;
}

__device__ __forceinline__ uint4 pack_h8(const F8& a) {
    __half2 h0 = __floats2half2_rn(a.v[0], a.v[1]);
    __half2 h1 = __floats2half2_rn(a.v[2], a.v[3]);
    __half2 h2 = __floats2half2_rn(a.v[4], a.v[5]);
    __half2 h3 = __floats2half2_rn(a.v[6], a.v[7]);
    uint4 pk;
    pk.x = *(const unsigned int*)&h0;
    pk.y = *(const unsigned int*)&h1;
    pk.z = *(const unsigned int*)&h2;
    pk.w = *(const unsigned int*)&h3;
    return pk;
}

// ---- 1. histogram of dst degrees (alone: it is on bucket's critical path) ----
__global__ void hist_kernel(const int* __restrict__ edge_dst) {
    int e = blockIdx.x * blockDim.x + threadIdx.x;
    if (e >= NUM_EDGES) return;
    atomicAdd(&g_deg[__ldg(edge_dst + e)], 1);
}

// ---- 2a. per-chunk sums ----
__global__ void block_sum_kernel() {
    __shared__ int s[SCAN_CHUNK];
    int t = threadIdx.x;
    int idx = blockIdx.x * SCAN_CHUNK + t;
    s[t] = (idx < NUM_NODES) ? g_deg[idx] : 0;
    __syncthreads();
    for (int o = SCAN_CHUNK / 2; o > 0; o >>= 1) {
        if (t < o) s[t] += s[t + o];
        __syncthreads();
    }
    if (t == 0) g_bsum[blockIdx.x] = s[0];
}

// ---- 2b. offsets: per-chunk scan + self-computed (lookback) chunk base ----
__global__ void offsets_kernel() {
    __shared__ int s[SCAN_CHUNK];
    __shared__ int base_sh;
    int t = threadIdx.x;

    // Phase A: base = sum of g_bsum[0 .. blockIdx.x-1]
    s[t] = (t < blockIdx.x) ? g_bsum[t] : 0;   // blockIdx.x <= 292 < 1024
    __syncthreads();
    for (int o = SCAN_CHUNK / 2; o > 0; o >>= 1) {
        if (t < o) s[t] += s[t + o];
        __syncthreads();
    }
    if (t == 0) base_sh = s[0];
    __syncthreads();

    // Phase B: chunk-local inclusive scan of degrees
    int idx = blockIdx.x * SCAN_CHUNK + t;
    int v = (idx < NUM_NODES) ? g_deg[idx] : 0;
    s[t] = v;
    __syncthreads();
    for (int o = 1; o < SCAN_CHUNK; o <<= 1) {
        int x = (t >= o) ? s[t - o] : 0;
        __syncthreads();
        s[t] += x;
        __syncthreads();
    }
    int excl = s[t] - v + base_sh;
    if (idx < NUM_NODES) {
        g_off[idx] = excl;
        g_pos[idx] = excl;
        if (idx == NUM_NODES - 1) g_off[NUM_NODES] = excl + v;
    }
}

#define BUCKET_PAIRS  ((NUM_EDGES + 1) / 2)                 // 1M threads, 2 edges each
#define BUCKET_BLOCKS ((BUCKET_PAIRS + 255) / 256)
#define CONV_THREADS  ((long long)NUM_NODES * 8)
#define CONV_BLOCKS   ((int)((CONV_THREADS + 255) / 256))

// ---- 3+0 fused: bucket (2 edges/thread, blocks [0, BUCKET_BLOCKS)) and
//      x0->fp16 convert (blocks [BUCKET_BLOCKS, BUCKET_BLOCKS+CONV_BLOCKS)).
// Bucket is latency-bound (atomic->store chain); convert is bandwidth-bound.
// Running them in one launch lets convert fill bucket's idle issue slots.
__global__ void bucket_convert_kernel(const int* __restrict__ edge_src,
                                      const int* __restrict__ edge_dst,
                                      const float* __restrict__ edge_weight,
                                      const float* __restrict__ u_embs,
                                      const float* __restrict__ i_embs) {
    if (blockIdx.x < BUCKET_BLOCKS) {
        int p2 = blockIdx.x * blockDim.x + threadIdx.x;
        int e0 = p2 * 2;
        if (e0 >= NUM_EDGES) return;
        if (e0 + 1 < NUM_EDGES) {
            // coalesced paired loads
            int2   d = *(const int2*)(edge_dst + e0);
            int2   s = *(const int2*)(edge_src + e0);
            float2 w = *(const float2*)(edge_weight + e0);
            // two independent atomic->store chains (overlapped latency)
            int pa = atomicAdd(&g_pos[d.x], 1);
            int pb = atomicAdd(&g_pos[d.y], 1);
            int2 ra; ra.x = s.x; ra.y = __float_as_int(w.x);
            int2 rb; rb.x = s.y; rb.y = __float_as_int(w.y);
            g_edge[pa] = ra;
            g_edge[pb] = rb;
        } else {
            int d = __ldg(edge_dst + e0);
            int p = atomicAdd(&g_pos[d], 1);
            int2 r;
            r.x = __ldg(edge_src + e0);
            r.y = __float_as_int(__ldg(edge_weight + e0));
            g_edge[p] = r;
        }
    } else {
        long long gid = (long long)(blockIdx.x - BUCKET_BLOCKS) * blockDim.x + threadIdx.x;
        if (gid >= CONV_THREADS) return;
        int n = (int)(gid >> 3);
        int c = (int)(gid & 7);
        const float* row = x0_row_ptr(n, u_embs, i_embs);
        float4 a = *(const float4*)(row + c * 8);
        float4 b = *(const float4*)(row + c * 8 + 4);
        F8 f;
        f.v[0] = a.x; f.v[1] = a.y; f.v[2] = a.z; f.v[3] = a.w;
        f.v[4] = b.x; f.v[5] = b.y; f.v[6] = b.z; f.v[7] = b.w;
        g_x0h[gid] = pack_h8(f);
    }
}

// ---- 4. layer-1 gather: 8 lanes/node, fp16 rows in and out (R9-exact) ----
__global__ void gather1_kernel() {
    long long gid = (long long)blockIdx.x * blockDim.x + threadIdx.x;
    int n = (int)(gid >> 3);
    int c = (int)(gid & 7);
    if (n >= NUM_NODES) return;

    int b = __ldg(&g_off[n]);
    int e = __ldg(&g_off[n + 1]);
    F8 acc;
    #pragma unroll
    for (int i = 0; i < 8; i++) acc.v[i] = 0.f;

    int k = b;
    for (; k + 1 < e; k += 2) {
        int2 e0 = g_edge[k], e1 = g_edge[k + 1];
        uint4 p0 = g_x0h[(size_t)e0.x * 8 + c];
        uint4 p1 = g_x0h[(size_t)e1.x * 8 + c];
        float w0 = __int_as_float(e0.y), w1 = __int_as_float(e1.y);
        F8 v0 = unpack_h8(p0), v1 = unpack_h8(p1);
        #pragma unroll
        for (int i = 0; i < 8; i++)
            acc.v[i] += w0 * v0.v[i] + w1 * v1.v[i];
    }
    if (k < e) {
        int2 e0 = g_edge[k];
        float w0 = __int_as_float(e0.y);
        F8 v0 = unpack_h8(g_x0h[(size_t)e0.x * 8 + c]);
        #pragma unroll
        for (int i = 0; i < 8; i++)
            acc.v[i] += w0 * v0.v[i];
    }
    g_x1h[(size_t)n * 8 + c] = pack_h8(acc);
}

// ---- 5. layer-2 gather (fp16 rows) fused with finalize (fp32 x0 + out), R9-exact ----
__global__ void gather2_fin_kernel(const float* __restrict__ u_embs,
                                   const float* __restrict__ i_embs,
                                   float* __restrict__ out) {
    long long gid = (long long)blockIdx.x * blockDim.x + threadIdx.x;
    int n = (int)(gid >> 3);
    int c = (int)(gid & 7);
    if (n >= NUM_NODES) return;

    int b = __ldg(&g_off[n]);
    int e = __ldg(&g_off[n + 1]);
    F8 acc;
    #pragma unroll
    for (int i = 0; i < 8; i++) acc.v[i] = 0.f;

    int k = b;
    for (; k + 1 < e; k += 2) {
        int2 e0 = g_edge[k], e1 = g_edge[k + 1];
        uint4 p0 = g_x1h[(size_t)e0.x * 8 + c];
        uint4 p1 = g_x1h[(size_t)e1.x * 8 + c];
        float w0 = __int_as_float(e0.y), w1 = __int_as_float(e1.y);
        F8 v0 = unpack_h8(p0), v1 = unpack_h8(p1);
        #pragma unroll
        for (int i = 0; i < 8; i++)
            acc.v[i] += w0 * v0.v[i] + w1 * v1.v[i];
    }
    if (k < e) {
        int2 e0 = g_edge[k];
        float w0 = __int_as_float(e0.y);
        F8 v0 = unpack_h8(g_x1h[(size_t)e0.x * 8 + c]);
        #pragma unroll
        for (int i = 0; i < 8; i++)
            acc.v[i] += w0 * v0.v[i];
    }

    // finalize: fp32 x0 row (accuracy) + fp16 x1 row + acc
    const float* x0_row = x0_row_ptr(n, u_embs, i_embs);
    float4 a0 = *(const float4*)(x0_row + c * 8);
    float4 a1 = *(const float4*)(x0_row + c * 8 + 4);
    F8 b1 = unpack_h8(g_x1h[(size_t)n * 8 + c]);

    const float inv3 = 1.0f / 3.0f;
    float4 r0, r1;
    r0.x = (a0.x + b1.v[0] + acc.v[0]) * inv3;
    r0.y = (a0.y + b1.v[1] + acc.v[1]) * inv3;
    r0.z = (a0.z + b1.v[2] + acc.v[2]) * inv3;
    r0.w = (a0.w + b1.v[3] + acc.v[3]) * inv3;
    r1.x = (a1.x + b1.v[4] + acc.v[4]) * inv3;
    r1.y = (a1.y + b1.v[5] + acc.v[5]) * inv3;
    r1.z = (a1.z + b1.v[6] + acc.v[6]) * inv3;
    r1.w = (a1.w + b1.v[7] + acc.v[7]) * inv3;
    *(float4*)(out + (size_t)n * EMBED_DIM + c * 8)     = r0;
    *(float4*)(out + (size_t)n * EMBED_DIM + c * 8 + 4) = r1;
}

extern "C" void kernel_launch(void* const* d_in, const int* in_sizes, int n_in,
                              void* d_out, int out_size) {
    const float* u_embs      = (const float*)d_in[0];
    const float* i_embs      = (const float*)d_in[1];
    const int*   edge_src    = (const int*)d_in[2];
    const int*   edge_dst    = (const int*)d_in[3];
    const float* edge_weight = (const float*)d_in[4];
    float* out = (float*)d_out;

    void* deg_ptr = nullptr;
    cudaGetSymbolAddress(&deg_ptr, g_deg);
    cudaMemsetAsync(deg_ptr, 0, NUM_NODES * sizeof(int), 0);

    // histogram (critical path for bucket)
    hist_kernel<<<(NUM_EDGES + 255) / 256, 256>>>(edge_dst);

    // chunk sums, then offsets with self-computed base
    block_sum_kernel<<<NUM_SCAN_BLOCKS, SCAN_CHUNK>>>();
    offsets_kernel<<<NUM_SCAN_BLOCKS, SCAN_CHUNK>>>();

    // fused bucket (2 edges/thread) + x0->fp16 convert
    bucket_convert_kernel<<<BUCKET_BLOCKS + CONV_BLOCKS, 256>>>(
        edge_src, edge_dst, edge_weight, u_embs, i_embs);

    // layer 1 gather (fp16 in/out, 8 lanes per node)
    {
        long long total = (long long)NUM_NODES * 8;
        int threads = 256;
        int blocks = (int)((total + threads - 1) / threads);
        gather1_kernel<<<blocks, threads>>>();
    }

    // layer 2 gather + finalize
    {
        long long total = (long long)NUM_NODES * 8;
        int threads = 256;
        int blocks = (int)((total + threads - 1) / threads);
        gather2_fin_kernel<<<blocks, threads>>>(u_embs, i_embs, out);
    }
}

// round 15
// speedup vs baseline: 1.0399x; 1.0042x over previous
#include <cuda_runtime.h>
#include <cuda_fp16.h>
#include <cstdint>

#define NUM_USERS 200000
#define NUM_ITEMS 100000
#define NUM_NODES (NUM_USERS + NUM_ITEMS)
#define EMBED_DIM 64
#define NUM_EDGES 2000000

#define SCAN_CHUNK 1024
#define NUM_SCAN_BLOCKS ((NUM_NODES + SCAN_CHUNK - 1) / SCAN_CHUNK)  // 293

// ---- device-global scratch (no allocation allowed) ----
// NOTE: g_deg is zero at module load and is RE-ZEROED by gather1_kernel at the
// end of every invocation (offsets_kernel is its last reader), so no memset is
// needed on the critical path. Deterministic across graph replays.
__device__ int   g_deg[NUM_NODES];
__device__ int   g_off[NUM_NODES + 1];
__device__ int   g_pos[NUM_NODES];
__device__ int   g_bsum[512];
__device__ int2  g_edge[NUM_EDGES];                 // packed (src, weight-bits)
__device__ uint4 g_x0h[(size_t)NUM_NODES * 8];      // x0 in fp16: 8 halves per uint4
__device__ uint4 g_x1h[(size_t)NUM_NODES * 8];      // x1 in fp16

__device__ __forceinline__ const float* x0_row_ptr(int s, const float* u, const float* it) {
    return (s < NUM_USERS) ? (u + (size_t)s * EMBED_DIM)
                           : (it + (size_t)(s - NUM_USERS) * EMBED_DIM);
}

struct F8 { float v[8]; };

__device__ __forceinline__ F8 unpack_h8(uint4 pk) {
    F8 r;
    float2 f0 = __half22float2(*(const __half2*)&pk.x);
    float2 f1 = __half22float2(*(const __half2*)&pk.y);
    float2 f2 = __half22float2(*(const __half2*)&pk.z);
    float2 f3 = __half22float2(*(const __half2*)&pk.w);
    r.v[0] = f0.x; r.v[1] = f0.y; r.v[2] = f1.x; r.v[3] = f1.y;
    r.v[4] = f2.x; r.v[5] = f2.y; r.v[6] = f3.x; r.v[7] = f3.y;
    return r;
}

__device__ __forceinline__ uint4 pack_h8(const F8& a) {
    __half2 h0 = __floats2half2_rn(a.v[0], a.v[1]);
    __half2 h1 = __floats2half2_rn(a.v[2], a.v[3]);
    __half2 h2 = __floats2half2_rn(a.v[4], a.v[5]);
    __half2 h3 = __floats2half2_rn(a.v[6], a.v[7]);
    uint4 pk;
    pk.x = *(const unsigned int*)&h0;
    pk.y = *(const unsigned int*)&h1;
    pk.z = *(const unsigned int*)&h2;
    pk.w = *(const unsigned int*)&h3;
    return pk;
}

// ---- 1. histogram of dst degrees: 2 edges/thread, fire-and-forget REDs ----
__global__ void hist_kernel(const int* __restrict__ edge_dst) {
    int t = blockIdx.x * blockDim.x + threadIdx.x;
    int e0 = t * 2;
    if (e0 >= NUM_EDGES) return;
    int2 d = *(const int2*)(edge_dst + e0);   // NUM_EDGES % 2 == 0
    atomicAdd(&g_deg[d.x], 1);
    atomicAdd(&g_deg[d.y], 1);
}

// ---- 2a. per-chunk sums ----
__global__ void block_sum_kernel() {
    __shared__ int s[SCAN_CHUNK];
    int t = threadIdx.x;
    int idx = blockIdx.x * SCAN_CHUNK + t;
    s[t] = (idx < NUM_NODES) ? g_deg[idx] : 0;
    __syncthreads();
    for (int o = SCAN_CHUNK / 2; o > 0; o >>= 1) {
        if (t < o) s[t] += s[t + o];
        __syncthreads();
    }
    if (t == 0) g_bsum[blockIdx.x] = s[0];
}

// ---- 2b. offsets: per-chunk scan + self-computed (lookback) chunk base ----
__global__ void offsets_kernel() {
    __shared__ int s[SCAN_CHUNK];
    __shared__ int base_sh;
    int t = threadIdx.x;

    // Phase A: base = sum of g_bsum[0 .. blockIdx.x-1]
    s[t] = (t < blockIdx.x) ? g_bsum[t] : 0;   // blockIdx.x <= 292 < 1024
    __syncthreads();
    for (int o = SCAN_CHUNK / 2; o > 0; o >>= 1) {
        if (t < o) s[t] += s[t + o];
        __syncthreads();
    }
    if (t == 0) base_sh = s[0];
    __syncthreads();

    // Phase B: chunk-local inclusive scan of degrees
    int idx = blockIdx.x * SCAN_CHUNK + t;
    int v = (idx < NUM_NODES) ? g_deg[idx] : 0;
    s[t] = v;
    __syncthreads();
    for (int o = 1; o < SCAN_CHUNK; o <<= 1) {
        int x = (t >= o) ? s[t - o] : 0;
        __syncthreads();
        s[t] += x;
        __syncthreads();
    }
    int excl = s[t] - v + base_sh;
    if (idx < NUM_NODES) {
        g_off[idx] = excl;
        g_pos[idx] = excl;
        if (idx == NUM_NODES - 1) g_off[NUM_NODES] = excl + v;
    }
}

#define BUCKET_QUADS  (NUM_EDGES / 4)                       // 500K threads, 4 edges each
#define BUCKET_BLOCKS ((BUCKET_QUADS + 255) / 256)
#define CONV_THREADS  ((long long)NUM_NODES * 8)
#define CONV_BLOCKS   ((int)((CONV_THREADS + 255) / 256))

// ---- 3+0 fused: bucket (4 edges/thread) + x0->fp16 convert ----
__global__ void bucket_convert_kernel(const int* __restrict__ edge_src,
                                      const int* __restrict__ edge_dst,
                                      const float* __restrict__ edge_weight,
                                      const float* __restrict__ u_embs,
                                      const float* __restrict__ i_embs) {
    if (blockIdx.x < BUCKET_BLOCKS) {
        int q = blockIdx.x * blockDim.x + threadIdx.x;
        if (q >= BUCKET_QUADS) return;
        int e0 = q * 4;                                     // NUM_EDGES % 4 == 0
        int4   d = *(const int4*)(edge_dst + e0);
        int4   s = *(const int4*)(edge_src + e0);
        float4 w = *(const float4*)(edge_weight + e0);
        // four independent atomic->store chains
        int pa = atomicAdd(&g_pos[d.x], 1);
        int pb = atomicAdd(&g_pos[d.y], 1);
        int pc = atomicAdd(&g_pos[d.z], 1);
        int pd = atomicAdd(&g_pos[d.w], 1);
        int2 ra; ra.x = s.x; ra.y = __float_as_int(w.x);
        int2 rb; rb.x = s.y; rb.y = __float_as_int(w.y);
        int2 rc; rc.x = s.z; rc.y = __float_as_int(w.z);
        int2 rd; rd.x = s.w; rd.y = __float_as_int(w.w);
        g_edge[pa] = ra;
        g_edge[pb] = rb;
        g_edge[pc] = rc;
        g_edge[pd] = rd;
    } else {
        long long gid = (long long)(blockIdx.x - BUCKET_BLOCKS) * blockDim.x + threadIdx.x;
        if (gid >= CONV_THREADS) return;
        int n = (int)(gid >> 3);
        int c = (int)(gid & 7);
        const float* row = x0_row_ptr(n, u_embs, i_embs);
        float4 a = *(const float4*)(row + c * 8);
        float4 b = *(const float4*)(row + c * 8 + 4);
        F8 f;
        f.v[0] = a.x; f.v[1] = a.y; f.v[2] = a.z; f.v[3] = a.w;
        f.v[4] = b.x; f.v[5] = b.y; f.v[6] = b.z; f.v[7] = b.w;
        g_x0h[gid] = pack_h8(f);
    }
}

// ---- 4. layer-1 gather: 8 lanes/node, fp16 rows in and out.
//      Also re-zeroes g_deg for the next invocation (graph replay). ----
__global__ void gather1_kernel() {
    long long gid = (long long)blockIdx.x * blockDim.x + threadIdx.x;
    int n = (int)(gid >> 3);
    int c = (int)(gid & 7);
    if (n >= NUM_NODES) return;

    // re-zero degree array (offsets_kernel was its last reader this invocation)
    if (gid < NUM_NODES) g_deg[(int)gid] = 0;

    int b = __ldg(&g_off[n]);
    int e = __ldg(&g_off[n + 1]);
    F8 acc;
    #pragma unroll
    for (int i = 0; i < 8; i++) acc.v[i] = 0.f;

    int k = b;
    for (; k + 1 < e; k += 2) {
        int2 e0 = g_edge[k], e1 = g_edge[k + 1];
        uint4 p0 = g_x0h[(size_t)e0.x * 8 + c];
        uint4 p1 = g_x0h[(size_t)e1.x * 8 + c];
        float w0 = __int_as_float(e0.y), w1 = __int_as_float(e1.y);
        F8 v0 = unpack_h8(p0), v1 = unpack_h8(p1);
        #pragma unroll
        for (int i = 0; i < 8; i++)
            acc.v[i] += w0 * v0.v[i] + w1 * v1.v[i];
    }
    if (k < e) {
        int2 e0 = g_edge[k];
        float w0 = __int_as_float(e0.y);
        F8 v0 = unpack_h8(g_x0h[(size_t)e0.x * 8 + c]);
        #pragma unroll
        for (int i = 0; i < 8; i++)
            acc.v[i] += w0 * v0.v[i];
    }
    g_x1h[(size_t)n * 8 + c] = pack_h8(acc);
}

// ---- 5. layer-2 gather (fp16 rows) fused with finalize (fp32 x0 + out) ----
__global__ void gather2_fin_kernel(const float* __restrict__ u_embs,
                                   const float* __restrict__ i_embs,
                                   float* __restrict__ out) {
    long long gid = (long long)blockIdx.x * blockDim.x + threadIdx.x;
    int n = (int)(gid >> 3);
    int c = (int)(gid & 7);
    if (n >= NUM_NODES) return;

    int b = __ldg(&g_off[n]);
    int e = __ldg(&g_off[n + 1]);
    F8 acc;
    #pragma unroll
    for (int i = 0; i < 8; i++) acc.v[i] = 0.f;

    int k = b;
    for (; k + 1 < e; k += 2) {
        int2 e0 = g_edge[k], e1 = g_edge[k + 1];
        uint4 p0 = g_x1h[(size_t)e0.x * 8 + c];
        uint4 p1 = g_x1h[(size_t)e1.x * 8 + c];
        float w0 = __int_as_float(e0.y), w1 = __int_as_float(e1.y);
        F8 v0 = unpack_h8(p0), v1 = unpack_h8(p1);
        #pragma unroll
        for (int i = 0; i < 8; i++)
            acc.v[i] += w0 * v0.v[i] + w1 * v1.v[i];
    }
    if (k < e) {
        int2 e0 = g_edge[k];
        float w0 = __int_as_float(e0.y);
        F8 v0 = unpack_h8(g_x1h[(size_t)e0.x * 8 + c]);
        #pragma unroll
        for (int i = 0; i < 8; i++)
            acc.v[i] += w0 * v0.v[i];
    }

    // finalize: fp32 x0 row (accuracy) + fp16 x1 row + acc
    const float* x0_row = x0_row_ptr(n, u_embs, i_embs);
    float4 a0 = *(const float4*)(x0_row + c * 8);
    float4 a1 = *(const float4*)(x0_row + c * 8 + 4);
    F8 b1 = unpack_h8(g_x1h[(size_t)n * 8 + c]);

    const float inv3 = 1.0f / 3.0f;
    float4 r0, r1;
    r0.x = (a0.x + b1.v[0] + acc.v[0]) * inv3;
    r0.y = (a0.y + b1.v[1] + acc.v[1]) * inv3;
    r0.z = (a0.z + b1.v[2] + acc.v[2]) * inv3;
    r0.w = (a0.w + b1.v[3] + acc.v[3]) * inv3;
    r1.x = (a1.x + b1.v[4] + acc.v[4]) * inv3;
    r1.y = (a1.y + b1.v[5] + acc.v[5]) * inv3;
    r1.z = (a1.z + b1.v[6] + acc.v[6]) * inv3;
    r1.w = (a1.w + b1.v[7] + acc.v[7]) * inv3;
    *(float4*)(out + (size_t)n * EMBED_DIM + c * 8)     = r0;
    *(float4*)(out + (size_t)n * EMBED_DIM + c * 8 + 4) = r1;
}

extern "C" void kernel_launch(void* const* d_in, const int* in_sizes, int n_in,
                              void* d_out, int out_size) {
    const float* u_embs      = (const float*)d_in[0];
    const float* i_embs      = (const float*)d_in[1];
    const int*   edge_src    = (const int*)d_in[2];
    const int*   edge_dst    = (const int*)d_in[3];
    const float* edge_weight = (const float*)d_in[4];
    float* out = (float*)d_out;

    // histogram (g_deg zeroed by module-load init / previous invocation's gather1)
    {
        int nthr = NUM_EDGES / 2;
        hist_kernel<<<(nthr + 255) / 256, 256>>>(edge_dst);
    }

    // chunk sums, then offsets with self-computed base
    block_sum_kernel<<<NUM_SCAN_BLOCKS, SCAN_CHUNK>>>();
    offsets_kernel<<<NUM_SCAN_BLOCKS, SCAN_CHUNK>>>();

    // fused bucket (4 edges/thread) + x0->fp16 convert
    bucket_convert_kernel<<<BUCKET_BLOCKS + CONV_BLOCKS, 256>>>(
        edge_src, edge_dst, edge_weight, u_embs, i_embs);

    // layer 1 gather (fp16 in/out, 8 lanes per node; re-zeroes g_deg)
    {
        long long total = (long long)NUM_NODES * 8;
        int threads = 256;
        int blocks = (int)((total + threads - 1) / threads);
        gather1_kernel<<<blocks, threads>>>();
    }

    // layer 2 gather + finalize
    {
        long long total = (long long)NUM_NODES * 8;
        int threads = 256;
        int blocks = (int)((total + threads - 1) / threads);
        gather2_fin_kernel<<<blocks, threads>>>(u_embs, i_embs, out);
    }
}

// round 17
// speedup vs baseline: 1.0505x; 1.0102x over previous
#include <cuda_runtime.h>
#include <cuda_fp16.h>
#include <cstdint>

#define NUM_USERS 200000
#define NUM_ITEMS 100000
#define NUM_NODES (NUM_USERS + NUM_ITEMS)
#define EMBED_DIM 64
#define NUM_EDGES 2000000

#define SCAN_CHUNK 1024
#define NUM_SCAN_BLOCKS ((NUM_NODES + SCAN_CHUNK - 1) / SCAN_CHUNK)  // 293

// ---- device-global scratch (no allocation allowed) ----
// g_deg is zero at module load and re-zeroed by gather1_kernel every invocation
// (offsets phase is its last reader), so no memset is on the critical path.
__device__ int   g_deg[NUM_NODES];
__device__ int   g_off[NUM_NODES + 1];
__device__ int   g_pos[NUM_NODES];
__device__ int   g_bsum[512];
__device__ int2  g_edge[NUM_EDGES];                 // packed (src, weight-bits)
__device__ uint4 g_x0h[(size_t)NUM_NODES * 8];      // x0 in fp16: 8 halves per uint4
__device__ uint4 g_x1h[(size_t)NUM_NODES * 8];      // x1 in fp16

__device__ __forceinline__ const float* x0_row_ptr(int s, const float* u, const float* it) {
    return (s < NUM_USERS) ? (u + (size_t)s * EMBED_DIM)
                           : (it + (size_t)(s - NUM_USERS) * EMBED_DIM);
}

struct F8 { float v[8]; };

__device__ __forceinline__ F8 unpack_h8(uint4 pk) {
    F8 r;
    float2 f0 = __half22float2(*(const __half2*)&pk.x);
    float2 f1 = __half22float2(*(const __half2*)&pk.y);
    float2 f2 = __half22float2(*(const __half2*)&pk.z);
    float2 f3 = __half22float2(*(const __half2*)&pk.w);
    r.v[0] = f0.x; r.v[1] = f0.y; r.v[2] = f1.x; r.v[3] = f1.y;
    r.v[4] = f2.x; r.v[5] = f2.y; r.v[6] = f3.x; r.v[7] = f3.y;
    return r;
}

__device__ __forceinline__ uint4 pack_h8(const F8& a) {
    __half2 h0 = __floats2half2_rn(a.v[0], a.v[1]);
    __half2 h1 = __floats2half2_rn(a.v[2], a.v[3]);
    __half2 h2 = __floats2half2_rn(a.v[4], a.v[5]);
    __half2 h3 = __floats2half2_rn(a.v[6], a.v[7]);
    uint4 pk;
    pk.x = *(const unsigned int*)&h0;
    pk.y = *(const unsigned int*)&h1;
    pk.z = *(const unsigned int*)&h2;
    pk.w = *(const unsigned int*)&h3;
    return pk;
}

// convert lane: thread g owns node g>>3, chunk g&7 (8 fp32 -> 8 fp16)
__device__ __forceinline__ void conv_one(long long gid,
                                         const float* __restrict__ u_embs,
                                         const float* __restrict__ i_embs) {
    int n = (int)(gid >> 3);
    int c = (int)(gid & 7);
    const float* row = x0_row_ptr(n, u_embs, i_embs);
    float4 a = *(const float4*)(row + c * 8);
    float4 b = *(const float4*)(row + c * 8 + 4);
    F8 f;
    f.v[0] = a.x; f.v[1] = a.y; f.v[2] = a.z; f.v[3] = a.w;
    f.v[4] = b.x; f.v[5] = b.y; f.v[6] = b.z; f.v[7] = b.w;
    g_x0h[gid] = pack_h8(f);
}

#define CONV_TOTAL      ((long long)NUM_NODES * 8)          // 2.4M lanes
#define CONV_HALF       (CONV_TOTAL / 2)                    // 1.2M
#define CONV_HALF_BLOCKS ((int)((CONV_HALF + 255) / 256))

// ---- 1. histogram of dst degrees: 2 edges/thread, fire-and-forget REDs ----
__global__ void hist_kernel(const int* __restrict__ edge_dst) {
    int t = blockIdx.x * blockDim.x + threadIdx.x;
    int e0 = t * 2;
    if (e0 >= NUM_EDGES) return;
    int2 d = *(const int2*)(edge_dst + e0);   // NUM_EDGES % 2 == 0
    atomicAdd(&g_deg[d.x], 1);
    atomicAdd(&g_deg[d.y], 1);
}

// ---- 2a. per-chunk sums (blocks [0,293)) + conv half 1 (blocks after) ----
__global__ void block_sum_conv_kernel(const float* __restrict__ u_embs,
                                      const float* __restrict__ i_embs) {
    if (blockIdx.x < NUM_SCAN_BLOCKS) {
        __shared__ int s[SCAN_CHUNK / 4];   // 256-thread block: warp-strided reduce
        int t = threadIdx.x;
        // each block sums SCAN_CHUNK degrees with 256 threads (4 each)
        int base = blockIdx.x * SCAN_CHUNK;
        int sum = 0;
        #pragma unroll
        for (int i = 0; i < 4; i++) {
            int idx = base + t + i * 256;
            sum += (idx < NUM_NODES) ? g_deg[idx] : 0;
        }
        s[t] = sum;
        __syncthreads();
        for (int o = 128; o > 0; o >>= 1) {
            if (t < o) s[t] += s[t + o];
            __syncthreads();
        }
        if (t == 0) g_bsum[blockIdx.x] = s[0];
    } else {
        long long gid = (long long)(blockIdx.x - NUM_SCAN_BLOCKS) * blockDim.x + threadIdx.x;
        if (gid >= CONV_HALF) return;
        conv_one(gid, u_embs, i_embs);
    }
}

// ---- 2b. offsets (blocks [0,293)) + conv half 2 ----
__global__ void offsets_conv_kernel(const float* __restrict__ u_embs,
                                    const float* __restrict__ i_embs) {
    if (blockIdx.x < NUM_SCAN_BLOCKS) {
        __shared__ int s[SCAN_CHUNK];
        __shared__ int base_sh;
        int t = threadIdx.x;   // 1024 threads for scan blocks path? No: block is 1024.
        // Phase A: base = sum of g_bsum[0 .. blockIdx.x-1]
        s[t] = (t < blockIdx.x) ? g_bsum[t] : 0;   // blockIdx.x <= 292 < 1024
        __syncthreads();
        for (int o = SCAN_CHUNK / 2; o > 0; o >>= 1) {
            if (t < o) s[t] += s[t + o];
            __syncthreads();
        }
        if (t == 0) base_sh = s[0];
        __syncthreads();

        // Phase B: chunk-local inclusive scan of degrees
        int idx = blockIdx.x * SCAN_CHUNK + t;
        int v = (idx < NUM_NODES) ? g_deg[idx] : 0;
        s[t] = v;
        __syncthreads();
        for (int o = 1; o < SCAN_CHUNK; o <<= 1) {
            int x = (t >= o) ? s[t - o] : 0;
            __syncthreads();
            s[t] += x;
            __syncthreads();
        }
        int excl = s[t] - v + base_sh;
        if (idx < NUM_NODES) {
            g_off[idx] = excl;
            g_pos[idx] = excl;
            if (idx == NUM_NODES - 1) g_off[NUM_NODES] = excl + v;
        }
    } else {
        // conv half 2: 1024-thread blocks, 4 conv lanes per thread
        long long tbase = (long long)(blockIdx.x - NUM_SCAN_BLOCKS) * blockDim.x + threadIdx.x;
        long long gid = CONV_HALF + tbase;
        if (gid < CONV_TOTAL) conv_one(gid, u_embs, i_embs);
        gid += (long long)gridDim.x; // no-op guard (keeps structure simple)
    }
}

#define BUCKET_QUADS  (NUM_EDGES / 4)                       // 500K threads, 4 edges each
#define BUCKET_BLOCKS ((BUCKET_QUADS + 255) / 256)

// ---- 3. bucket edges by dst: 4 edges/thread, standalone (at L2-atomic floor) ----
__global__ void bucket_kernel(const int* __restrict__ edge_src,
                              const int* __restrict__ edge_dst,
                              const float* __restrict__ edge_weight) {
    int q = blockIdx.x * blockDim.x + threadIdx.x;
    if (q >= BUCKET_QUADS) return;
    int e0 = q * 4;                                         // NUM_EDGES % 4 == 0
    int4   d = *(const int4*)(edge_dst + e0);
    int4   s = *(const int4*)(edge_src + e0);
    float4 w = *(const float4*)(edge_weight + e0);
    int pa = atomicAdd(&g_pos[d.x], 1);
    int pb = atomicAdd(&g_pos[d.y], 1);
    int pc = atomicAdd(&g_pos[d.z], 1);
    int pd = atomicAdd(&g_pos[d.w], 1);
    int2 ra; ra.x = s.x; ra.y = __float_as_int(w.x);
    int2 rb; rb.x = s.y; rb.y = __float_as_int(w.y);
    int2 rc; rc.x = s.z; rc.y = __float_as_int(w.z);
    int2 rd; rd.x = s.w; rd.y = __float_as_int(w.w);
    g_edge[pa] = ra;
    g_edge[pb] = rb;
    g_edge[pc] = rc;
    g_edge[pd] = rd;
}

// ---- 4. layer-1 gather: 8 lanes/node, fp16 in/out; re-zeroes g_deg ----
__global__ void gather1_kernel() {
    long long gid = (long long)blockIdx.x * blockDim.x + threadIdx.x;
    int n = (int)(gid >> 3);
    int c = (int)(gid & 7);
    if (n >= NUM_NODES) return;

    if (gid < NUM_NODES) g_deg[(int)gid] = 0;   // reset for next invocation

    int b = __ldg(&g_off[n]);
    int e = __ldg(&g_off[n + 1]);
    F8 acc;
    #pragma unroll
    for (int i = 0; i < 8; i++) acc.v[i] = 0.f;

    int k = b;
    for (; k + 1 < e; k += 2) {
        int2 e0 = g_edge[k], e1 = g_edge[k + 1];
        uint4 p0 = g_x0h[(size_t)e0.x * 8 + c];
        uint4 p1 = g_x0h[(size_t)e1.x * 8 + c];
        float w0 = __int_as_float(e0.y), w1 = __int_as_float(e1.y);
        F8 v0 = unpack_h8(p0), v1 = unpack_h8(p1);
        #pragma unroll
        for (int i = 0; i < 8; i++)
            acc.v[i] += w0 * v0.v[i] + w1 * v1.v[i];
    }
    if (k < e) {
        int2 e0 = g_edge[k];
        float w0 = __int_as_float(e0.y);
        F8 v0 = unpack_h8(g_x0h[(size_t)e0.x * 8 + c]);
        #pragma unroll
        for (int i = 0; i < 8; i++)
            acc.v[i] += w0 * v0.v[i];
    }
    g_x1h[(size_t)n * 8 + c] = pack_h8(acc);
}

// ---- 5. layer-2 gather fused with finalize (x0 now read as fp16 too) ----
__global__ void gather2_fin_kernel(float* __restrict__ out) {
    long long gid = (long long)blockIdx.x * blockDim.x + threadIdx.x;
    int n = (int)(gid >> 3);
    int c = (int)(gid & 7);
    if (n >= NUM_NODES) return;

    int b = __ldg(&g_off[n]);
    int e = __ldg(&g_off[n + 1]);
    F8 acc;
    #pragma unroll
    for (int i = 0; i < 8; i++) acc.v[i] = 0.f;

    int k = b;
    for (; k + 1 < e; k += 2) {
        int2 e0 = g_edge[k], e1 = g_edge[k + 1];
        uint4 p0 = g_x1h[(size_t)e0.x * 8 + c];
        uint4 p1 = g_x1h[(size_t)e1.x * 8 + c];
        float w0 = __int_as_float(e0.y), w1 = __int_as_float(e1.y);
        F8 v0 = unpack_h8(p0), v1 = unpack_h8(p1);
        #pragma unroll
        for (int i = 0; i < 8; i++)
            acc.v[i] += w0 * v0.v[i] + w1 * v1.v[i];
    }
    if (k < e) {
        int2 e0 = g_edge[k];
        float w0 = __int_as_float(e0.y);
        F8 v0 = unpack_h8(g_x1h[(size_t)e0.x * 8 + c]);
        #pragma unroll
        for (int i = 0; i < 8; i++)
            acc.v[i] += w0 * v0.v[i];
    }

    // finalize: fp16 x0 + fp16 x1 + acc, /3 in fp32
    F8 a  = unpack_h8(g_x0h[(size_t)n * 8 + c]);
    F8 b1 = unpack_h8(g_x1h[(size_t)n * 8 + c]);

    const float inv3 = 1.0f / 3.0f;
    float4 r0, r1;
    r0.x = (a.v[0] + b1.v[0] + acc.v[0]) * inv3;
    r0.y = (a.v[1] + b1.v[1] + acc.v[1]) * inv3;
    r0.z = (a.v[2] + b1.v[2] + acc.v[2]) * inv3;
    r0.w = (a.v[3] + b1.v[3] + acc.v[3]) * inv3;
    r1.x = (a.v[4] + b1.v[4] + acc.v[4]) * inv3;
    r1.y = (a.v[5] + b1.v[5] + acc.v[5]) * inv3;
    r1.z = (a.v[6] + b1.v[6] + acc.v[6]) * inv3;
    r1.w = (a.v[7] + b1.v[7] + acc.v[7]) * inv3;
    *(float4*)(out + (size_t)n * EMBED_DIM + c * 8)     = r0;
    *(float4*)(out + (size_t)n * EMBED_DIM + c * 8 + 4) = r1;
}

extern "C" void kernel_launch(void* const* d_in, const int* in_sizes, int n_in,
                              void* d_out, int out_size) {
    const float* u_embs      = (const float*)d_in[0];
    const float* i_embs      = (const float*)d_in[1];
    const int*   edge_src    = (const int*)d_in[2];
    const int*   edge_dst    = (const int*)d_in[3];
    const float* edge_weight = (const float*)d_in[4];
    float* out = (float*)d_out;

    // 1. histogram (g_deg pre-zeroed)
    {
        int nthr = NUM_EDGES / 2;
        hist_kernel<<<(nthr + 255) / 256, 256>>>(edge_dst);
    }

    // 2a. chunk sums (256-thr blocks) + conv half 1 riding along
    block_sum_conv_kernel<<<NUM_SCAN_BLOCKS + CONV_HALF_BLOCKS, 256>>>(u_embs, i_embs);

    // 2b. offsets (1024-thr blocks) + conv half 2 riding along
    {
        int conv2_blocks = (int)((CONV_HALF + 1023) / 1024);
        offsets_conv_kernel<<<NUM_SCAN_BLOCKS + conv2_blocks, SCAN_CHUNK>>>(u_embs, i_embs);
    }

    // 3. bucket (standalone; at L2-atomic throughput floor)
    bucket_kernel<<<(BUCKET_QUADS + 255) / 256, 256>>>(edge_src, edge_dst, edge_weight);

    // 4. layer 1 gather
    {
        long long total = (long long)NUM_NODES * 8;
        gather1_kernel<<<(int)((total + 255) / 256), 256>>>();
    }

    // 5. layer 2 gather + finalize
    {
        long long total = (long long)NUM_NODES * 8;
        gather2_fin_kernel<<<(int)((total + 255) / 256), 256>>>(out);
    }
}